// round 3
// baseline (speedup 1.0000x reference)
#include <cuda_runtime.h>
#include <cstdio>
#include <cstdint>

#define KSEG 160
#define BATCH 1024

// ---------------- device scratch ----------------
__device__ float g_GIa[(size_t)KSEG * BATCH * 36];  // GRU1 input gates
__device__ float g_GIb[(size_t)KSEG * BATCH * 36];  // GRU2 input gates (with PE)
__device__ float g_out[(size_t)BATCH * KSEG * 12];  // GRU2 outputs
__device__ float g_hT[12];                          // debug: GRU1 final h for b=0

// ---------------- debug: input identification ----------------
__global__ void dbg_inputs(const float* x, int nx, const float* encW,
                           const float* Wih, const float* Whh,
                           const float* bih, const float* W1, const float* W2)
{
    if (threadIdx.x != 0) return;
    float sx = 0.f, sw = 0.f, s1 = 0.f, s2 = 0.f;
    int n = nx < 1024 ? nx : 1024;
    for (int i = 0; i < n; i++) sx += fabsf(x[i]);
    for (int i = 0; i < 432; i++) sw += fabsf(Wih[i]);
    for (int i = 0; i < 1024; i++) { s1 += fabsf(W1[i]); s2 += fabsf(W2[i]); }
    printf("HXDBG meanabs x=%.4f Wih=%.4f W1=%.4f W2=%.4f | heads x=%.4f,%.4f encW=%.4f Wih=%.4f Whh=%.4f bih=%.4f\n",
           sx / n, sw / 432.f, s1 / 1024.f, s2 / 1024.f,
           x[0], x[1], encW[0], Wih[0], Whh[0], bih[0]);
}

__global__ void dbg_post()
{
    if (threadIdx.x != 0) return;
    printf("HXDBG gia0=%.5f,%.5f,%.5f gib0=%.5f,%.5f,%.5f hT=%.5f,%.5f,%.5f,%.5f out00=%.5f,%.5f,%.5f,%.5f\n",
           g_GIa[0], g_GIa[1], g_GIa[2], g_GIb[0], g_GIb[1], g_GIb[2],
           g_hT[0], g_hT[1], g_hT[2], g_hT[3],
           g_out[0], g_out[1], g_out[2], g_out[3]);
}

// ---------------- prep: encoder + literal input gates (identical to R2) ----------------
__global__ void __launch_bounds__(128) prep_kernel(
    const float* __restrict__ x, const float* __restrict__ encW,
    const float* __restrict__ encb, const float* __restrict__ Wih,
    const float* __restrict__ bih)
{
    __shared__ float s_encW[144], s_encb[12], s_Wih[432], s_bih[36], s_pe[12];
    const int k = blockIdx.x;
    const int tid = threadIdx.x;

    for (int i = tid; i < 144; i += 128) s_encW[i] = encW[k * 144 + i];
    if (tid < 12) s_encb[tid] = encb[k * 12 + tid];
    for (int i = tid; i < 432; i += 128) s_Wih[i] = Wih[i];
    if (tid < 36) s_bih[tid] = bih[tid];
    if (tid < 12) {
        float pos = (float)k;
        float div = expf((float)(tid & ~1) * (-9.210340371976184f / 12.0f));
        float ang = pos * div;
        float v = (tid & 1) ? cosf(ang) : sinf(ang);
        s_pe[tid] = v + sinf(pos);
    }
    __syncthreads();

    if (k == 1 && blockIdx.y == 0 && tid == 0)
        printf("HXDBG pe(k=1)=%.5f,%.5f,%.5f,%.5f\n", s_pe[0], s_pe[1], s_pe[2], s_pe[3]);

    const int b = blockIdx.y * 128 + tid;

    const float4* xp = reinterpret_cast<const float4*>(x + (size_t)b * 1920 + k * 12);
    float4 v0 = xp[0], v1 = xp[1], v2 = xp[2];
    float xb[12] = {v0.x, v0.y, v0.z, v0.w, v1.x, v1.y, v1.z, v1.w, v2.x, v2.y, v2.z, v2.w};
    float xs[12];
#pragma unroll
    for (int o = 0; o < 12; o++) {
        float a = s_encb[o];
#pragma unroll
        for (int i = 0; i < 12; i++) a = fmaf(xb[i], s_encW[i * 12 + o], a);
        xs[o] = fmaxf(a, 0.0f);
    }

    float ga[36], gb[36];
#pragma unroll
    for (int g = 0; g < 36; g++) {
        float aa = s_bih[g];
        float ab = s_bih[g];
#pragma unroll
        for (int i = 0; i < 12; i++) {
            float w = s_Wih[g * 12 + i];
            aa = fmaf(xs[i], w, aa);
            ab = fmaf(xs[i] + s_pe[i], w, ab);
        }
        ga[g] = aa;
        gb[g] = ab;
    }
    float4* oa = reinterpret_cast<float4*>(g_GIa + ((size_t)k * BATCH + b) * 36);
    float4* ob = reinterpret_cast<float4*>(g_GIb + ((size_t)k * BATCH + b) * 36);
#pragma unroll
    for (int q = 0; q < 9; q++) {
        oa[q] = make_float4(ga[4 * q], ga[4 * q + 1], ga[4 * q + 2], ga[4 * q + 3]);
        ob[q] = make_float4(gb[4 * q], gb[4 * q + 1], gb[4 * q + 2], gb[4 * q + 3]);
    }
}

// ---------------- sequential GRU (identical to R2) ----------------
__device__ __forceinline__ float dot12(const float* h, const float* w, float init)
{
    float a0 = fmaf(h[1], w[1], h[0] * w[0]);
    float a1 = fmaf(h[3], w[3], h[2] * w[2]);
    float a2 = fmaf(h[5], w[5], h[4] * w[4]);
    float a3 = fmaf(h[7], w[7], h[6] * w[6]);
    float a4 = fmaf(h[9], w[9], h[8] * w[8]);
    float a5 = fmaf(h[11], w[11], h[10] * w[10]);
    float b0 = a0 + a1;
    float b1 = a2 + a3;
    float b2 = a4 + a5;
    return (b0 + b1) + (b2 + init);
}

template <bool STORE>
__device__ __forceinline__ void gru_phase(const float* __restrict__ gi, int b, int u, int lane,
                                          float* h, const float* WR, const float* WZ,
                                          const float* WN, float br, float bz, float bn,
                                          float* __restrict__ outp)
{
    const float* p0 = gi + (size_t)b * 36;
    const size_t KS = (size_t)BATCH * 36;
    float ir = p0[u], iz = p0[12 + u], inn = p0[24 + u];
#pragma unroll 1
    for (int k = 0; k < 160; k++) {
        const float* pn_ = p0 + (size_t)((k + 1 < 160) ? (k + 1) : k) * KS;
        float nir = pn_[u], niz = pn_[12 + u], ninn = pn_[24 + u];

        float hr = dot12(h, WR, br);
        float hz = dot12(h, WZ, bz);
        float hn = dot12(h, WN, bn);
        float r = 1.0f / (1.0f + __expf(-(ir + hr)));
        float z = 1.0f / (1.0f + __expf(-(iz + hz)));
        float n = tanhf(fmaf(r, hn, inn));
        float hnew = fmaf(z, h[u] - n, n);
#pragma unroll
        for (int i = 0; i < 12; i++) h[i] = __shfl_sync(0xffffffffu, hnew, i);
        if (STORE && lane < 12) outp[(size_t)k * 12 + u] = hnew;

        ir = nir; iz = niz; inn = ninn;
    }
}

__global__ void __launch_bounds__(32) gru_kernel(const float* __restrict__ Whh,
                                                 const float* __restrict__ bhh)
{
    const int b = blockIdx.x;
    const int lane = threadIdx.x;
    const int u = lane % 12;
    float WR[12], WZ[12], WN[12];
#pragma unroll
    for (int i = 0; i < 12; i++) {
        WR[i] = Whh[u * 12 + i];
        WZ[i] = Whh[(u + 12) * 12 + i];
        WN[i] = Whh[(u + 24) * 12 + i];
    }
    const float br = bhh[u], bz = bhh[12 + u], bn = bhh[24 + u];
    float h[12];
#pragma unroll
    for (int i = 0; i < 12; i++) h[i] = 0.0f;
    float* outp = g_out + (size_t)b * 160 * 12;
    gru_phase<false>(g_GIa, b, u, lane, h, WR, WZ, WN, br, bz, bn, nullptr);
    if (b == 0 && lane < 12) g_hT[lane] = h[lane];   // debug snapshot
    gru_phase<true>(g_GIb, b, u, lane, h, WR, WZ, WN, br, bz, bn, outp);
}

// ---------------- LITERAL decoder (bisect: no algebraic collapse) ----------------
// hid[b,k,h] = b1[k,h] + sum_d out[b,k,d]*W1[k,d,h]
// res[b,k,o] = b2[k,o] + sum_h hid[b,k,h]*W2[k,h,o]
__global__ void __launch_bounds__(1024) dec_lit_kernel(
    const float* __restrict__ W1, const float* __restrict__ b1,
    const float* __restrict__ W2, const float* __restrict__ b2,
    float* __restrict__ out)
{
    const int k = blockIdx.x;
    const int b = threadIdx.x;
    const float* hp = g_out + ((size_t)b * 160 + k) * 12;
    float hv[12];
#pragma unroll
    for (int i = 0; i < 12; i++) hv[i] = hp[i];
    float res[12];
#pragma unroll
    for (int o = 0; o < 12; o++) res[o] = b2[k * 12 + o];
    const float* w1 = W1 + (size_t)k * 12288;  // [d][h]
    const float* w2 = W2 + (size_t)k * 12288;  // [h][o]
    const float* bb = b1 + (size_t)k * 1024;
#pragma unroll 4
    for (int h = 0; h < 1024; h++) {
        float hid = bb[h];
#pragma unroll
        for (int d = 0; d < 12; d++) hid = fmaf(hv[d], w1[d * 1024 + h], hid);
#pragma unroll
        for (int o = 0; o < 12; o++) res[o] = fmaf(hid, w2[h * 12 + o], res[o]);
    }
    float* op = out + (size_t)b * 1920 + k * 12;
#pragma unroll
    for (int o = 0; o < 12; o++) op[o] = res[o];
}

// ---------------- launch ----------------
extern "C" void kernel_launch(void* const* d_in, const int* in_sizes, int n_in,
                              void* d_out, int out_size)
{
    (void)out_size;
    printf("HXDBG n_in=%d sizes:", n_in);
    for (int i = 0; i < n_in; i++) printf(" %d", in_sizes[i]);
    printf(" (expect 1966080 23040 1920 432 432 36 36 1966080 163840 1966080 1920)\n");

    const float* x    = (const float*)d_in[0];
    const float* encW = (const float*)d_in[1];
    const float* encb = (const float*)d_in[2];
    const float* Wih  = (const float*)d_in[3];
    const float* Whh  = (const float*)d_in[4];
    const float* bih  = (const float*)d_in[5];
    const float* bhh  = (const float*)d_in[6];
    const float* W1   = (const float*)d_in[7];
    const float* b1   = (const float*)d_in[8];
    const float* W2   = (const float*)d_in[9];
    const float* b2   = (const float*)d_in[10];
    float* out = (float*)d_out;

    dbg_inputs<<<1, 1>>>(x, in_sizes[0], encW, Wih, Whh, bih, W1, W2);
    prep_kernel<<<dim3(160, 8), 128>>>(x, encW, encb, Wih, bih);
    gru_kernel<<<1024, 32>>>(Whh, bhh);
    dbg_post<<<1, 1>>>();
    dec_lit_kernel<<<160, 1024>>>(W1, b1, W2, b2, out);
}

// round 4
// speedup vs baseline: 5.4728x; 5.4728x over previous
#include <cuda_runtime.h>
#include <cstdint>

#define KSEG 160
#define BATCH 1024

// ---------------- device scratch (no allocation allowed) ----------------
__device__ float g_GIa[(size_t)KSEG * BATCH * 36];  // GRU1 pre-scaled input gates
__device__ float g_GIb[(size_t)KSEG * BATCH * 36];  // GRU2 pre-scaled input gates (PE folded)
__device__ float g_M[KSEG * 144];                   // collapsed decoder, [k][o][d]
__device__ float g_c[KSEG * 12];                    // collapsed decoder bias
__device__ float g_out[(size_t)BATCH * KSEG * 12];  // GRU2 outputs, [b][k][u]

__device__ __forceinline__ float ex2f_(float x) { float y; asm("ex2.approx.f32 %0, %1;" : "=f"(y) : "f"(x)); return y; }
__device__ __forceinline__ float rcpf_(float x) { float y; asm("rcp.approx.f32 %0, %1;" : "=f"(y) : "f"(x)); return y; }

#define L2E 1.4426950408889634f

// ---------------- prep: encoder + pre-scaled input gates for both phases ----------------
// gates layout per (k,b): [0..11]=-L2E*(ir+bih_r+bhh_r), [12..23]=-L2E*(iz+bih_z+bhh_z),
//                         [24..35]=-2L2E*(inn+bih_n)
__global__ void __launch_bounds__(128) prep_kernel(
    const float* __restrict__ x, const float* __restrict__ encW,
    const float* __restrict__ encb, const float* __restrict__ Wih,
    const float* __restrict__ bih, const float* __restrict__ bhh)
{
    __shared__ float s_encW[144], s_encb[12], s_Wih[432], s_base[36], s_pe[12];
    const int k = blockIdx.x;
    const int tid = threadIdx.x;

    for (int i = tid; i < 144; i += 128) s_encW[i] = encW[k * 144 + i];
    if (tid < 12) s_encb[tid] = encb[k * 12 + tid];
    for (int i = tid; i < 432; i += 128) s_Wih[i] = Wih[i];
    if (tid < 36) s_base[tid] = bih[tid] + (tid < 24 ? bhh[tid] : 0.0f);
    if (tid < 12) {
        // pos_enc (sinusoidal, d=12) + channel_enc (= sin(k) broadcast)
        float pos = (float)k;
        float div = expf((float)(tid & ~1) * (-9.210340371976184f / 12.0f));
        float ang = pos * div;
        float v = (tid & 1) ? cosf(ang) : sinf(ang);
        s_pe[tid] = v + sinf(pos);
    }
    __syncthreads();

    const int b = blockIdx.y * 128 + tid;

    // encoder: xs = relu(xb @ encW[k] + encb[k])
    const float4* xp = reinterpret_cast<const float4*>(x + (size_t)b * 1920 + k * 12);
    float4 v0 = xp[0], v1 = xp[1], v2 = xp[2];
    float xb[12] = {v0.x, v0.y, v0.z, v0.w, v1.x, v1.y, v1.z, v1.w, v2.x, v2.y, v2.z, v2.w};
    float xs[12];
#pragma unroll
    for (int o = 0; o < 12; o++) {
        float a = s_encb[o];
#pragma unroll
        for (int i = 0; i < 12; i++) a = fmaf(xb[i], s_encW[i * 12 + o], a);
        xs[o] = fmaxf(a, 0.0f);
    }

    float ga[36], gb[36];
#pragma unroll
    for (int g = 0; g < 36; g++) {
        float aa = s_base[g];
        float ab = s_base[g];
#pragma unroll
        for (int i = 0; i < 12; i++) {
            float w = s_Wih[g * 12 + i];
            aa = fmaf(xs[i], w, aa);
            ab = fmaf(xs[i] + s_pe[i], w, ab);
        }
        float scl = (g < 24) ? -L2E : -2.0f * L2E;
        ga[g] = scl * aa;
        gb[g] = scl * ab;
    }
    float4* oa = reinterpret_cast<float4*>(g_GIa + ((size_t)k * BATCH + b) * 36);
    float4* ob = reinterpret_cast<float4*>(g_GIb + ((size_t)k * BATCH + b) * 36);
#pragma unroll
    for (int q = 0; q < 9; q++) {
        oa[q] = make_float4(ga[4 * q], ga[4 * q + 1], ga[4 * q + 2], ga[4 * q + 3]);
        ob[q] = make_float4(gb[4 * q], gb[4 * q + 1], gb[4 * q + 2], gb[4 * q + 3]);
    }
}

// ---------------- decmat: collapse decoder to 12x12 per segment ----------------
__global__ void __launch_bounds__(160) decmat_kernel(
    const float* __restrict__ W1, const float* __restrict__ b1,
    const float* __restrict__ W2, const float* __restrict__ b2)
{
    const int k = blockIdx.x, t = threadIdx.x;
    if (t < 144) {
        const int o = t / 12, d = t % 12;
        const float* w1 = W1 + ((size_t)k * 12 + d) * 1024;
        const float* w2 = W2 + (size_t)k * 12288 + o;
        float acc = 0.0f;
#pragma unroll 8
        for (int h = 0; h < 1024; h++) acc = fmaf(w1[h], w2[(size_t)h * 12], acc);
        g_M[k * 144 + t] = acc;  // [k][o][d]
    } else if (t < 156) {
        const int o = t - 144;
        const float* bb = b1 + (size_t)k * 1024;
        const float* w2 = W2 + (size_t)k * 12288 + o;
        float acc = b2[k * 12 + o];
#pragma unroll 8
        for (int h = 0; h < 1024; h++) acc = fmaf(bb[h], w2[(size_t)h * 12], acc);
        g_c[k * 12 + o] = acc;
    }
}

// ---------------- sequential GRU (log2-domain fast gates), 1 warp per batch ----------------
__device__ __forceinline__ float dot12(const float* h, const float* w, float init)
{
    float a0 = fmaf(h[1], w[1], h[0] * w[0]);
    float a1 = fmaf(h[3], w[3], h[2] * w[2]);
    float a2 = fmaf(h[5], w[5], h[4] * w[4]);
    float a3 = fmaf(h[7], w[7], h[6] * w[6]);
    float a4 = fmaf(h[9], w[9], h[8] * w[8]);
    float a5 = fmaf(h[11], w[11], h[10] * w[10]);
    float b0 = a0 + a1;
    float b1 = a2 + a3;
    float b2 = a4 + a5;
    return (b0 + b1) + (b2 + init);
}

template <bool STORE>
__device__ __forceinline__ void gru_phase(const float* __restrict__ gi, int b, int u, int lane,
                                          float* h, const float* WR, const float* WZ,
                                          const float* WN, float bn,
                                          float* __restrict__ outp)
{
    const float* p0 = gi + (size_t)b * 36;
    const size_t KS = (size_t)BATCH * 36;
    float gr = p0[u], gz = p0[12 + u], gn = p0[24 + u];
#pragma unroll 1
    for (int k = 0; k < 160; k++) {
        // 1-step-ahead prefetch: loads independent of the recurrence chain
        const float* pn_ = p0 + (size_t)((k + 1 < 160) ? (k + 1) : k) * KS;
        float ngr = pn_[u], ngz = pn_[12 + u], ngn = pn_[24 + u];

        float tr = dot12(h, WR, gr);                    // = -L2E*(ir+hr+b)
        float tz = dot12(h, WZ, gz);                    // = -L2E*(iz+hz+b)
        float tn = dot12(h, WN, bn);                    // = -2L2E*(hn+bhh_n)
        float r = rcpf_(1.0f + ex2f_(tr));              // sigmoid
        float z = rcpf_(1.0f + ex2f_(tz));
        float na = fmaf(r, tn, gn);                     // = -2L2E*(inn+bih_n + r*(hn+bhh_n))
        float n = fmaf(2.0f, rcpf_(1.0f + ex2f_(na)), -1.0f);  // tanh
        float hnew = fmaf(z, h[u] - n, n);
#pragma unroll
        for (int i = 0; i < 12; i++) h[i] = __shfl_sync(0xffffffffu, hnew, i);
        if (STORE && lane < 12) outp[(size_t)k * 12 + u] = hnew;

        gr = ngr; gz = ngz; gn = ngn;
    }
}

__global__ void __launch_bounds__(32) gru_kernel(const float* __restrict__ Whh,
                                                 const float* __restrict__ bhh)
{
    const int b = blockIdx.x;
    const int lane = threadIdx.x;
    const int u = lane % 12;
    float WR[12], WZ[12], WN[12];
#pragma unroll
    for (int i = 0; i < 12; i++) {
        WR[i] = -L2E * Whh[u * 12 + i];
        WZ[i] = -L2E * Whh[(u + 12) * 12 + i];
        WN[i] = -2.0f * L2E * Whh[(u + 24) * 12 + i];
    }
    const float bn = -2.0f * L2E * bhh[24 + u];
    float h[12];
#pragma unroll
    for (int i = 0; i < 12; i++) h[i] = 0.0f;
    float* outp = g_out + (size_t)b * 160 * 12;
    gru_phase<false>(g_GIa, b, u, lane, h, WR, WZ, WN, bn, nullptr);  // GRU1: keep h_T
    gru_phase<true>(g_GIb, b, u, lane, h, WR, WZ, WN, bn, outp);      // GRU2: emit ys
}

// ---------------- decoder apply: res = out @ M[k] + c[k] ----------------
__global__ void __launch_bounds__(128) dec_kernel(float* __restrict__ out)
{
    __shared__ float sM[144], sc[12];
    const int k = blockIdx.x, tid = threadIdx.x;
    for (int i = tid; i < 144; i += 128) sM[i] = g_M[k * 144 + i];   // FIXED: full 144 loaded
    if (tid < 12) sc[tid] = g_c[k * 12 + tid];
    __syncthreads();

    const int b = blockIdx.y * 128 + tid;
    const float4* hp = reinterpret_cast<const float4*>(g_out + ((size_t)b * 160 + k) * 12);
    float4 a0 = hp[0], a1 = hp[1], a2 = hp[2];
    float hv[12] = {a0.x, a0.y, a0.z, a0.w, a1.x, a1.y, a1.z, a1.w, a2.x, a2.y, a2.z, a2.w};
    float ov[12];
#pragma unroll
    for (int o = 0; o < 12; o++) {
        float acc = sc[o];
#pragma unroll
        for (int d = 0; d < 12; d++) acc = fmaf(hv[d], sM[o * 12 + d], acc);
        ov[o] = acc;
    }
    float4* op = reinterpret_cast<float4*>(out + (size_t)b * 1920 + k * 12);
    op[0] = make_float4(ov[0], ov[1], ov[2], ov[3]);
    op[1] = make_float4(ov[4], ov[5], ov[6], ov[7]);
    op[2] = make_float4(ov[8], ov[9], ov[10], ov[11]);
}

// ---------------- launch ----------------
extern "C" void kernel_launch(void* const* d_in, const int* in_sizes, int n_in,
                              void* d_out, int out_size)
{
    (void)in_sizes; (void)n_in; (void)out_size;
    const float* x    = (const float*)d_in[0];
    const float* encW = (const float*)d_in[1];
    const float* encb = (const float*)d_in[2];
    const float* Wih  = (const float*)d_in[3];
    const float* Whh  = (const float*)d_in[4];
    const float* bih  = (const float*)d_in[5];
    const float* bhh  = (const float*)d_in[6];
    const float* W1   = (const float*)d_in[7];
    const float* b1   = (const float*)d_in[8];
    const float* W2   = (const float*)d_in[9];
    const float* b2   = (const float*)d_in[10];
    float* out = (float*)d_out;

    prep_kernel<<<dim3(160, 8), 128>>>(x, encW, encb, Wih, bih, bhh);
    decmat_kernel<<<160, 160>>>(W1, b1, W2, b2);
    gru_kernel<<<1024, 32>>>(Whh, bhh);
    dec_kernel<<<dim3(160, 8), 128>>>(out);
}